// round 9
// baseline (speedup 1.0000x reference)
#include <cuda_runtime.h>
#include <cstdint>
#include <cstddef>

#define TS   64
#define BS   16
#define NP   1024
#define DIN  32
#define DOUT 16
#define HID  64
#define NW   8        // warps per block
#define NTHR (NW*32)
#define BPB  37       // blocks per batch
#define NBLK (BS*BPB) // 592 = 4 * 148 -> exactly one wave at 4 blocks/SM

// ---- persistent scratch ---------------------------------------------------
static __device__ float    g_x[2][BS*NP*DIN];
static __device__ float    g_s[BS*NP];
static __device__ uint32_t g_keys[TS-1][2];
static __device__ float    g_sv[DIN];
static __device__ float    g_vy[DOUT];
static __device__ float    g_Kd[DOUT];
static __device__ float    g_cg[DIN];
static __device__ uint32_t g_rotm[16];
static __device__ unsigned g_bar;     // grid-barrier arrive counter
static __device__ unsigned g_rel;     // grid-barrier release generation

// ---- threefry2x32 (reference form, init only) ------------------------------
__device__ __forceinline__ uint32_t rotl32(uint32_t x, uint32_t d) {
    return (x << d) | (x >> (32u - d));
}

__device__ __forceinline__ void tf2x32(uint32_t k0, uint32_t k1,
                                       uint32_t x0, uint32_t x1,
                                       uint32_t& o0, uint32_t& o1)
{
    uint32_t k2 = k0 ^ k1 ^ 0x1BD11BDAu;
    x0 += k0; x1 += k1;
#define TFR0(r) { x0 += x1; x1 = rotl32(x1, r); x1 ^= x0; }
    TFR0(13) TFR0(15) TFR0(26) TFR0(6)
    x0 += k1; x1 += k2 + 1u;
    TFR0(17) TFR0(29) TFR0(16) TFR0(24)
    x0 += k2; x1 += k0 + 2u;
    TFR0(13) TFR0(15) TFR0(26) TFR0(6)
    x0 += k0; x1 += k1 + 3u;
    TFR0(17) TFR0(29) TFR0(16) TFR0(24)
    x0 += k1; x1 += k2 + 4u;
    TFR0(13) TFR0(15) TFR0(26) TFR0(6)
    x0 += k2; x1 += k0 + 5u;
#undef TFR0
    o0 = x0; o1 = x1;
}

// gumbel = -log(-log(uniform(tiny,1))) — exact JAX arithmetic
__device__ __forceinline__ float gumbel_from_bits(uint32_t w)
{
    float f = __uint_as_float(0x3f800000u | (w >> 9)) - 1.0f;
    float u = f + 1.17549435e-38f;
    return -logf(-logf(u));
}

// ---- fast cipher (all rotates via IMAD.WIDE on fma pipe) -------------------
__device__ __forceinline__ uint32_t tf_fast(
    uint32_t x1, uint32_t k0,
    uint32_t m13, uint32_t m15, uint32_t m26, uint32_t m6,
    uint32_t m17, uint32_t m29, uint32_t m16, uint32_t m24,
    uint32_t one,
    uint32_t kA1, uint32_t kB1, uint32_t kA2, uint32_t kB2,
    uint32_t kA3, uint32_t kB3, uint32_t kA4, uint32_t kB4,
    uint32_t kA5, uint32_t kB5)
{
    uint32_t x0 = k0;
#define RMAD(m) { x0 = x1*one + x0; uint64_t p = (uint64_t)x1*(uint64_t)(m); \
                  x1 = (((uint32_t)p) | ((uint32_t)(p>>32))) ^ x0; }
#define RADD(m) { x0 = x0 + x1;     uint64_t p = (uint64_t)x1*(uint64_t)(m); \
                  x1 = (((uint32_t)p) | ((uint32_t)(p>>32))) ^ x0; }
    RMAD(m13) RMAD(m15) RMAD(m26) RADD(m6)
    x0 += kA1; x1 += kB1;
    RMAD(m17) RMAD(m29) RMAD(m16) RADD(m24)
    x0 += kA2; x1 += kB2;
    RMAD(m13) RMAD(m15) RMAD(m26) RADD(m6)
    x0 += kA3; x1 += kB3;
    RMAD(m17) RMAD(m29) RMAD(m16) RADD(m24)
    x0 += kA4; x1 += kB4;
    RMAD(m13) RMAD(m15) RMAD(m26) RADD(m6)
    x0 += kA5; x1 += kB5;
#undef RMAD
#undef RADD
    return x0 ^ x1;
}

// ---- init -----------------------------------------------------------------
__global__ void init_kernel(const float* __restrict__ lvx,
                            const float* __restrict__ lvy,
                            const float* __restrict__ gb1,
                            const float* __restrict__ gW2,
                            const float* __restrict__ gb2)
{
    int t = threadIdx.x;
    if (t < DIN)  g_sv[t] = sqrtf(expf(lvx[t]));
    if (t < DOUT) {
        float v = expf(lvy[t]);
        g_vy[t] = v;
        g_Kd[t] = logf(__fmul_rn(6.283185307179586f, v));
    }
    if (t < DIN) {
        float a = 0.f;
        for (int h = 0; h < HID; h++) {
            float hv = fmaxf(gb1[h], 0.f);
            a = fmaf(hv, gW2[h*DIN + t], a);
        }
        g_cg[t] = __fadd_rn(a, gb2[t]);
    }
    if (t < TS-1) {
        uint32_t o0, o1;
        tf2x32(0u, 1u, 0u, (uint32_t)t, o0, o1);
        g_keys[t][0] = o0; g_keys[t][1] = o1;
    }
    if (t == 0) {
        const int rr[8] = {13, 15, 26, 6, 17, 29, 16, 24};
        for (int i = 0; i < 8; i++) g_rotm[i] = 1u << rr[i];
        g_rotm[8] = 1u;
        g_bar = 0u;
        g_rel = 0u;
    }
}

// ---- grid-wide barrier (all NBLK blocks co-resident by construction) -------
__device__ __forceinline__ void grid_sync(unsigned expect)
{
    __syncthreads();
    if (threadIdx.x == 0) {
        __threadfence();
        unsigned a = atomicAdd(&g_bar, 1u) + 1u;
        if (a == (unsigned)NBLK) {
            atomicExch(&g_bar, 0u);
            __threadfence();
            atomicAdd(&g_rel, 1u);
        } else {
            while (*(volatile unsigned*)&g_rel < expect) __nanosleep(64);
        }
        __threadfence();
    }
    __syncthreads();
}

// ---- persistent kernel: all 64 steps, one launch ---------------------------
__global__ void __launch_bounds__(NTHR, 4) pers_kernel(
    const float* __restrict__ eps_std,
    const float* __restrict__ y,
    const float* __restrict__ gW1, const float* __restrict__ gb1,
    const float* __restrict__ gW2, const float* __restrict__ gb2,
    const float* __restrict__ fW1, const float* __restrict__ fb1,
    const float* __restrict__ fW2, const float* __restrict__ fb2,
    float* __restrict__ out)
{
    __shared__ __align__(16) float s_lw[NP];
    __shared__ float s_y[DOUT], s_vy[DOUT], s_Kd[DOUT];
    __shared__ float s_x[NW][DIN], s_h[NW][HID], s_yh[NW][DOUT];

    const int tid  = threadIdx.x;
    const int w    = tid >> 5, lane = tid & 31;
    const int bid  = blockIdx.x;
    const int b    = bid / BPB;          // batch owned by this block
    const int sub  = bid % BPB;
    const int n0   = (sub * NP) / BPB;   // row range [n0, n1) within batch
    const int n1   = ((sub + 1) * NP) / BPB;

    const float NEG_INF = __int_as_float(0xff800000);
    // constants hoisted for the whole run
    const uint32_t m13 = g_rotm[0], m15 = g_rotm[1], m26 = g_rotm[2], m6  = g_rotm[3];
    const uint32_t m17 = g_rotm[4], m29 = g_rotm[5], m16 = g_rotm[6], m24 = g_rotm[7];
    const uint32_t one = g_rotm[8];
    const float LN2U = 0.6931473f;
    const float svl = g_sv[lane];
    const float cgl = g_cg[lane];
    if (tid < DOUT) { s_vy[tid] = g_vy[tid]; s_Kd[tid] = g_Kd[tid]; }

    for (int t = 0; t < TS; t++) {
        const int cur = t & 1, prv = cur ^ 1;

        if (tid < DOUT)
            s_y[tid] = __ldg(&y[((size_t)t*BS + b)*DOUT + tid]);

        // per-block log_softmax of batch b (exact R1 single-warp chain)
        if (t > 0 && w == 0) {
            const float* s = &g_s[b*NP];
            float m = NEG_INF;
            for (int c = lane; c < NP; c += 32) m = fmaxf(m, __ldcg(s + c));
            #pragma unroll
            for (int off = 16; off; off >>= 1)
                m = fmaxf(m, __shfl_xor_sync(0xffffffffu, m, off));
            float p = 0.f;
            for (int c = lane; c < NP; c += 32)
                p = __fadd_rn(p, expf(__ldcg(s + c) - m));
            #pragma unroll
            for (int off = 16; off; off >>= 1)
                p = __fadd_rn(p, __shfl_down_sync(0xffffffffu, p, off));
            float L = logf(p);
            L = __shfl_sync(0xffffffffu, L, 0);
            for (int c = lane; c < NP; c += 32)
                s_lw[c] = (__ldcg(s + c) - m) - L;
        }
        __syncthreads();

        // per-step key material
        uint32_t k0 = 0, kA1=0,kB1=0,kA2=0,kB2=0,kA3=0,kB3=0,kA4=0,kB4=0,kA5=0,kB5=0;
        uint32_t k1add = 0;
        if (t > 0) {
            k0 = g_keys[t-1][0];
            const uint32_t k1 = g_keys[t-1][1];
            const uint32_t k2 = k0 ^ k1 ^ 0x1BD11BDAu;
            kA1 = k1; kB1 = k2 + 1u;
            kA2 = k2; kB2 = k0 + 2u;
            kA3 = k0; kB3 = k1 + 3u;
            kA4 = k1; kB4 = k2 + 4u;
            kA5 = k2; kB5 = k0 + 5u;
            k1add = k1;
        }

        for (int n = n0 + w; n < n1; n += NW) {
            const int row = b*NP + n;
            const float* eps = &eps_std[(((size_t)t*BS + b)*NP + n)*DIN];
            float xr;

            if (t == 0) {
                xr = __fadd_rn(cgl, __fmul_rn(__ldg(eps + lane), svl));
            } else {
                // ---- categorical: FLO-pruned gumbel-argmax, ILP=2 ----------
                const float2* lwp = (const float2*)s_lw;
                float best = NEG_INF;
                float bps  = NEG_INF;
                int   bidx = NP;
                uint32_t bk = (((uint32_t)row) << 10) + k1add + (uint32_t)(2*lane);

                #pragma unroll 1
                for (int i = 0; i < NP/64; i++, bk += 64u) {
                    const int c = i*64 + 2*lane;
                    uint32_t bits1 = tf_fast(bk,      k0, m13,m15,m26,m6,m17,m29,m16,m24,one,
                                             kA1,kB1,kA2,kB2,kA3,kB3,kA4,kB4,kA5,kB5);
                    uint32_t bits2 = tf_fast(bk + 1u, k0, m13,m15,m26,m6,m17,m29,m16,m24,one,
                                             kA1,kB1,kA2,kB2,kA3,kB3,kA4,kB4,kA5,kB5);
                    const float2 lw = lwp[i*32 + lane];
                    // gumbel(bits) <= -log(1-u) < (j+1)*ln2, j = leading ones
                    const int j1 = __clz(~bits1);
                    const int j2 = __clz(~bits2);
                    const float ub1 = fmaf((float)(j1 + 1), LN2U, lw.x);
                    const float ub2 = fmaf((float)(j2 + 1), LN2U, lw.y);
                    const bool c1 = ub1 > bps, c2 = ub2 > bps;
                    if (__any_sync(0xffffffffu, c1 | c2)) {
                        if (c1) {
                            float sc = gumbel_from_bits(bits1) + lw.x;
                            if (sc > best) { best = sc; bidx = c; }
                        }
                        if (c2) {
                            float sc = gumbel_from_bits(bits2) + lw.y;
                            if (sc > best) { best = sc; bidx = c + 1; }
                        }
                        float mm = best;
                        #pragma unroll
                        for (int off = 16; off; off >>= 1)
                            mm = fmaxf(mm, __shfl_xor_sync(0xffffffffu, mm, off));
                        bps = mm - 0.011f;
                    }
                }
                #pragma unroll
                for (int off = 16; off; off >>= 1) {
                    float ob = __shfl_xor_sync(0xffffffffu, best, off);
                    int   oi = __shfl_xor_sync(0xffffffffu, bidx, off);
                    if (ob > best || (ob == best && oi < bidx)) { best = ob; bidx = oi; }
                }
                const int p = bidx;

                // ---- gather parent + g-FFN (exact chains) ----
                float xv = __ldcg(&g_x[prv][((size_t)(b*NP + p))*DIN + lane]);
                s_x[w][lane] = xv;
                __syncwarp();
                float a0 = 0.f, a1 = 0.f;
                const float* w1 = gW1 + lane;
                #pragma unroll
                for (int k = 0; k < DIN; k++) {
                    float xk = s_x[w][k];
                    a0 = fmaf(xk, __ldg(w1 + k*HID),      a0);
                    a1 = fmaf(xk, __ldg(w1 + k*HID + 32), a1);
                }
                s_h[w][lane]      = fmaxf(__fadd_rn(a0, __ldg(gb1 + lane)),      0.f);
                s_h[w][lane + 32] = fmaxf(__fadd_rn(a1, __ldg(gb1 + lane + 32)), 0.f);
                __syncwarp();
                float a = 0.f;
                const float* w2 = gW2 + lane;
                #pragma unroll
                for (int h = 0; h < HID; h++)
                    a = fmaf(s_h[w][h], __ldg(w2 + h*DIN), a);
                float go = __fadd_rn(a, __ldg(gb2 + lane));
                xr = __fadd_rn(go, __fmul_rn(__ldg(eps + lane), svl));
                __syncwarp();
            }

            __stcg(&g_x[cur][((size_t)row)*DIN + lane], xr);
            s_x[w][lane] = xr;
            __syncwarp();

            // ---- f-FFN ----
            {
                float a0 = 0.f, a1 = 0.f;
                const float* w1 = fW1 + lane;
                #pragma unroll
                for (int k = 0; k < DIN; k++) {
                    float xk = s_x[w][k];
                    a0 = fmaf(xk, __ldg(w1 + k*HID),      a0);
                    a1 = fmaf(xk, __ldg(w1 + k*HID + 32), a1);
                }
                s_h[w][lane]      = fmaxf(__fadd_rn(a0, __ldg(fb1 + lane)),      0.f);
                s_h[w][lane + 32] = fmaxf(__fadd_rn(a1, __ldg(fb1 + lane + 32)), 0.f);
            }
            __syncwarp();
            if (lane < DOUT) {
                float a = 0.f;
                const float* w2 = fW2 + lane;
                #pragma unroll
                for (int h = 0; h < HID; h++)
                    a = fmaf(s_h[w][h], __ldg(w2 + h*DOUT), a);
                float yh = __fadd_rn(a, __ldg(fb2 + lane));
                out[((size_t)row + (size_t)t*BS*NP)*DOUT + lane] = yh;
                s_yh[w][lane] = yh;
            }
            __syncwarp();
            if (lane == 0) {
                float acc = 0.f;
                #pragma unroll
                for (int j = 0; j < DOUT; j++) {
                    float yh = s_yh[w][j];
                    float d2 = yh - s_y[j];
                    float q  = __fdiv_rn(__fmul_rn(d2, d2), s_vy[j]);
                    acc = __fadd_rn(acc, __fadd_rn(q, s_Kd[j]));
                }
                __stcg(&g_s[row], __fmul_rn(-0.5f, acc));
            }
            __syncwarp();
        }

        if (t < TS-1) grid_sync((unsigned)(t + 1));
    }
}

// ---- launch ---------------------------------------------------------------
extern "C" void kernel_launch(void* const* d_in, const int* in_sizes, int n_in,
                              void* d_out, int out_size)
{
    (void)in_sizes; (void)n_in; (void)out_size;
    const float* y    = (const float*)d_in[1];
    const float* eps  = (const float*)d_in[2];
    const float* lvx  = (const float*)d_in[3];
    const float* lvy  = (const float*)d_in[4];
    const float* gW1  = (const float*)d_in[5];
    const float* gb1  = (const float*)d_in[6];
    const float* gW2  = (const float*)d_in[7];
    const float* gb2  = (const float*)d_in[8];
    const float* fW1  = (const float*)d_in[9];
    const float* fb1  = (const float*)d_in[10];
    const float* fW2  = (const float*)d_in[11];
    const float* fb2  = (const float*)d_in[12];
    float* out = (float*)d_out;

    init_kernel<<<1, 64>>>(lvx, lvy, gb1, gW2, gb2);
    pers_kernel<<<NBLK, NTHR>>>(eps, y, gW1, gb1, gW2, gb2,
                                fW1, fb1, fW2, fb2, out);
}